// round 13
// baseline (speedup 1.0000x reference)
#include <cuda_runtime.h>
#include <cstdint>

// score[e] = dot(h[src[e]], h[dst[e]]), D_FEAT = 128 (fp32).
// R10 finding: L1tex=83.7% is the binder. Gathers have ~zero L1 reuse
// (each h row touched <1x per SM), so every line pays a fill-write into the
// L1 data array plus the read-out wavefront -> 2x port traffic -> ~96us floor
// (matches measured 94us). Fix: __ldcg (L2-only, no L1 allocate) on the row
// gathers removes the fill writes. Predicted ~65-75us, L2 becomes the binder.

static constexpr int D_FEAT = 128;
static constexpr int EPW = 8;          // edges per warp
static constexpr int WARPS_PER_BLOCK = 8;

__global__ void __launch_bounds__(256)
edge_dot8_kernel(const float* __restrict__ h,
                 const int* __restrict__ src,
                 const int* __restrict__ dst,
                 float* __restrict__ out,
                 int n_edges)
{
    const int warp = (int)((blockIdx.x * (unsigned)blockDim.x + threadIdx.x) >> 5);
    const int lane = threadIdx.x & 31;
    const int e0 = warp * EPW;
    if (e0 >= n_edges) return;

    if (e0 + EPW <= n_edges) {
        // ---- fast path: full batch of 8 edges ----
        // Lane-parallel index fetch: lanes 0-7 read src[e0..e0+7],
        // lanes 8-15 read dst[e0..e0+7]. One LDG, 1-2 sectors.
        int v = 0;
        if (lane < 16) {
            const int* p = (lane < 8) ? (src + e0 + lane) : (dst + e0 + (lane - 8));
            v = __ldg(p);
        }
        int s[EPW], d[EPW];
        #pragma unroll
        for (int i = 0; i < EPW; i++) {
            s[i] = __shfl_sync(0xffffffffu, v, i);
            d[i] = __shfl_sync(0xffffffffu, v, 8 + i);
        }

        // Issue all 16 gathers before consuming anything -> 16 outstanding
        // LDG.128 per lane slot. __ldcg: L2-only, no L1 fill (zero reuse).
        float4 a[EPW], b[EPW];
        #pragma unroll
        for (int i = 0; i < EPW; i++)
            a[i] = __ldcg(reinterpret_cast<const float4*>(
                       h + (size_t)s[i] * D_FEAT) + lane);
        #pragma unroll
        for (int i = 0; i < EPW; i++)
            b[i] = __ldcg(reinterpret_cast<const float4*>(
                       h + (size_t)d[i] * D_FEAT) + lane);

        float sum[EPW];
        #pragma unroll
        for (int i = 0; i < EPW; i++)
            sum[i] = a[i].x * b[i].x + a[i].y * b[i].y
                   + a[i].z * b[i].z + a[i].w * b[i].w;

        // 8 independent butterfly reductions (pipelined shuffles).
        #pragma unroll
        for (int off = 16; off > 0; off >>= 1) {
            #pragma unroll
            for (int i = 0; i < EPW; i++)
                sum[i] += __shfl_xor_sync(0xffffffffu, sum[i], off);
        }

        // All lanes hold the totals; lanes 0 and 1 each store one float4.
        if (lane < 2) {
            float4 o = (lane == 0)
                ? make_float4(sum[0], sum[1], sum[2], sum[3])
                : make_float4(sum[4], sum[5], sum[6], sum[7]);
            *reinterpret_cast<float4*>(out + e0 + 4 * lane) = o;
        }
    } else {
        // ---- tail: scalar per-edge path ----
        for (int e = e0; e < n_edges; e++) {
            const int s = __ldg(src + e);
            const int d = __ldg(dst + e);
            const float4 a = __ldcg(reinterpret_cast<const float4*>(
                                 h + (size_t)s * D_FEAT) + lane);
            const float4 b = __ldcg(reinterpret_cast<const float4*>(
                                 h + (size_t)d * D_FEAT) + lane);
            float sum = a.x * b.x + a.y * b.y + a.z * b.z + a.w * b.w;
            #pragma unroll
            for (int off = 16; off > 0; off >>= 1)
                sum += __shfl_xor_sync(0xffffffffu, sum, off);
            if (lane == 0) out[e] = sum;
        }
    }
}

extern "C" void kernel_launch(void* const* d_in, const int* in_sizes, int n_in,
                              void* d_out, int out_size)
{
    const float* h = (const float*)d_in[0];          // [N_NODES, 128] fp32
    const int* edge_index = (const int*)d_in[1];     // [2, E] int32

    const int n_edges = in_sizes[1] / 2;
    const int* src = edge_index;                     // row 0
    const int* dst = edge_index + n_edges;           // row 1

    float* out = (float*)d_out;                      // [E, 1] fp32

    const int threads = 32 * WARPS_PER_BLOCK;        // 256
    const int edges_per_block = WARPS_PER_BLOCK * EPW;  // 64
    const int blocks = (n_edges + edges_per_block - 1) / edges_per_block;

    edge_dot8_kernel<<<blocks, threads>>>(h, src, dst, out, n_edges);
}